// round 6
// baseline (speedup 1.0000x reference)
#include <cuda_runtime.h>
#include <float.h>

// Shapes (fixed): network_mesh (4,3,32,32) f32 = d_in[0]; pc (4,3,4096) f32 = d_in[1].
// Output: scalar f32 = mean over 4*4096 nearest-refined-mesh squared distances.
#define B_       4
#define H_       32
#define W_       32
#define FAC_     3
#define OH_      94          // (32-1)*3+1
#define OW_      94
#define NMESH_   (OH_ * OW_) // 8836
#define M_       4096
#define SLICES_  74
#define SLICE_   120         // 73*120=8760, last slice = 76
#define THREADS_ 256
#define RPT_     4           // pc point PAIRS per thread (4 pairs = 8 points)
#define CHUNKS_  2           // 4096 pts / (256 thr * 8 pts)
#define R1BLOCKS_ 64

// Allocation-free scratch.
__device__ float g_partial[SLICES_ * B_ * M_];   // per-slice per-point minima (incl |p|^2)
__device__ float g_sums[R1BLOCKS_];

union df2 { unsigned long long u; float2 f; };

__device__ __forceinline__ unsigned long long pack2(float lo, float hi) {
    df2 t; t.f = make_float2(lo, hi); return t.u;
}

// Packed dual-FMA (Blackwell f32x2 path). NOTE: no packed f32 min exists in PTX.
__device__ __forceinline__ unsigned long long fma2(unsigned long long a,
                                                   unsigned long long b,
                                                   unsigned long long c) {
    unsigned long long r;
    asm("fma.rn.f32x2 %0, %1, %2, %3;" : "=l"(r) : "l"(a), "l"(b), "l"(c));
    return r;
}

// ---------------------------------------------------------------------------
// Kernel 1: fused refine (inline, per-slice) + nearest-point partial minima.
// grid = (B, CHUNKS, SLICES) = (4,2,74) = 592 blocks = 4 CTAs/SM (32 warps/SM).
// smem holds the slice duplicated per lane-pair: sa[j]={xx,yy}, sb[j]={zz,ww}.
// Register diet: |p|^2 is NOT kept live across the hot loop; it is recomputed
// in the epilogue from a fresh pc reload (L2-hot), keeping regs <= 64 so 4 CTAs
// can co-reside per SM.
// ---------------------------------------------------------------------------
__global__ __launch_bounds__(THREADS_, 4)
void dist_kernel(const float* __restrict__ mesh, const float* __restrict__ pc) {
    __shared__ ulonglong2 sa[SLICE_];   // {x,x},{y,y}
    __shared__ ulonglong2 sb[SLICE_];   // {z,z},{w,w}  w = |m|^2

    const int b     = blockIdx.x;
    const int chunk = blockIdx.y;
    const int s     = blockIdx.z;

    const int base = s * SLICE_;
    const int cnt  = (base + SLICE_ <= NMESH_) ? SLICE_ : (NMESH_ - base);

    // --- Inline bilinear refine (align_corners, factor 3) for this slice ---
    const float* __restrict__ m0 = mesh + (b * 3 + 0) * H_ * W_;
    const float* __restrict__ m1 = mesh + (b * 3 + 1) * H_ * W_;
    const float* __restrict__ m2 = mesh + (b * 3 + 2) * H_ * W_;

    if (threadIdx.x < cnt) {
        int i = threadIdx.x;                 // SLICE_ <= THREADS_, one pass
        int idx = base + i;
        int r = idx / OW_;
        int c = idx - r * OW_;
        int y0 = r / FAC_; if (y0 > H_ - 2) y0 = H_ - 2;
        int x0 = c / FAC_; if (x0 > W_ - 2) x0 = W_ - 2;
        float wy = (float)r / (float)FAC_ - (float)y0;
        float wx = (float)c / (float)FAC_ - (float)x0;
        int o00 = y0 * W_ + x0, o01 = o00 + 1, o10 = o00 + W_, o11 = o10 + 1;

        float t0 = m0[o00] * (1.0f - wx) + m0[o01] * wx;
        float u0 = m0[o10] * (1.0f - wx) + m0[o11] * wx;
        float v0 = t0 * (1.0f - wy) + u0 * wy;

        float t1 = m1[o00] * (1.0f - wx) + m1[o01] * wx;
        float u1 = m1[o10] * (1.0f - wx) + m1[o11] * wx;
        float v1 = t1 * (1.0f - wy) + u1 * wy;

        float t2 = m2[o00] * (1.0f - wx) + m2[o01] * wx;
        float u2 = m2[o10] * (1.0f - wx) + m2[o11] * wx;
        float v2 = t2 * (1.0f - wy) + u2 * wy;

        float w = fmaf(v0, v0, fmaf(v1, v1, v2 * v2));

        sa[i] = make_ulonglong2(pack2(v0, v0), pack2(v1, v1));
        sb[i] = make_ulonglong2(pack2(v2, v2), pack2(w, w));
    }
    __syncthreads();

    // --- Load this thread's pc point pairs (only -2p kept live in the loop) ---
    const float* __restrict__ px = pc + (b * 3 + 0) * M_;
    const float* __restrict__ py = pc + (b * 3 + 1) * M_;
    const float* __restrict__ pz = pc + (b * 3 + 2) * M_;

    const int q0 = chunk * (THREADS_ * RPT_) + threadIdx.x;   // pair index

    unsigned long long ax2[RPT_], ay2[RPT_], az2[RPT_];
    float b0[RPT_], b1[RPT_];
#pragma unroll
    for (int r = 0; r < RPT_; r++) {
        int q = q0 + r * THREADS_;
        float2 x = *(const float2*)(px + 2 * q);
        float2 y = *(const float2*)(py + 2 * q);
        float2 z = *(const float2*)(pz + 2 * q);
        ax2[r] = pack2(-2.0f * x.x, -2.0f * x.y);
        ay2[r] = pack2(-2.0f * y.x, -2.0f * y.y);
        az2[r] = pack2(-2.0f * z.x, -2.0f * z.y);
        b0[r] = FLT_MAX;
        b1[r] = FLT_MAX;
    }

    // --- Hot loop: t = fma2(xx,ax, fma2(yy,ay, fma2(zz,az, ww))); scalar min ---
#pragma unroll 2
    for (int j = 0; j < cnt; j++) {
        ulonglong2 A = sa[j];   // broadcast LDS.128
        ulonglong2 Bv = sb[j];
#pragma unroll
        for (int r = 0; r < RPT_; r++) {
            df2 t;
            t.u = fma2(A.x, ax2[r], fma2(A.y, ay2[r], fma2(Bv.x, az2[r], Bv.y)));
            b0[r] = fminf(b0[r], t.f.x);
            b1[r] = fminf(b1[r], t.f.y);
        }
    }

    // --- Epilogue: recompute |p|^2 (reload pc, L2-hot) and emit partials ---
#pragma unroll
    for (int r = 0; r < RPT_; r++) {
        int q = q0 + r * THREADS_;
        float2 x = *(const float2*)(px + 2 * q);
        float2 y = *(const float2*)(py + 2 * q);
        float2 z = *(const float2*)(pz + 2 * q);
        float2 out;
        out.x = b0[r] + fmaf(x.x, x.x, fmaf(y.x, y.x, z.x * z.x));
        out.y = b1[r] + fmaf(x.y, x.y, fmaf(y.y, y.y, z.y * z.y));
        *(float2*)(g_partial + (s * B_ + b) * M_ + 2 * q) = out;
    }
}

// ---------------------------------------------------------------------------
// Kernel 2: per-point min across slices + per-block deterministic tree sum.
// ---------------------------------------------------------------------------
__global__ __launch_bounds__(THREADS_)
void reduce1_kernel() {
    __shared__ float red[THREADS_];
    const int i = blockIdx.x * THREADS_ + threadIdx.x;   // i < 16384
    float v = g_partial[i];
#pragma unroll
    for (int s = 1; s < SLICES_; s++)
        v = fminf(v, g_partial[s * (B_ * M_) + i]);
    red[threadIdx.x] = v;
    __syncthreads();
#pragma unroll
    for (int off = THREADS_ / 2; off > 0; off >>= 1) {
        if (threadIdx.x < off) red[threadIdx.x] += red[threadIdx.x + off];
        __syncthreads();
    }
    if (threadIdx.x == 0) g_sums[blockIdx.x] = red[0];
}

// ---------------------------------------------------------------------------
// Kernel 3: final deterministic sum of 64 partials + mean.
// ---------------------------------------------------------------------------
__global__ void reduce2_kernel(float* __restrict__ out) {
    __shared__ float red[R1BLOCKS_];
    red[threadIdx.x] = g_sums[threadIdx.x];
    __syncthreads();
#pragma unroll
    for (int off = R1BLOCKS_ / 2; off > 0; off >>= 1) {
        if (threadIdx.x < off) red[threadIdx.x] += red[threadIdx.x + off];
        __syncthreads();
    }
    if (threadIdx.x == 0) out[0] = red[0] / (float)(B_ * M_);
}

// ---------------------------------------------------------------------------
extern "C" void kernel_launch(void* const* d_in, const int* in_sizes, int n_in,
                              void* d_out, int out_size) {
    const float* mesh = (const float*)d_in[0];
    const float* pc   = (const float*)d_in[1];
    float* out = (float*)d_out;

    dim3 grid(B_, CHUNKS_, SLICES_);
    dist_kernel<<<grid, THREADS_>>>(mesh, pc);
    reduce1_kernel<<<R1BLOCKS_, THREADS_>>>();
    reduce2_kernel<<<1, R1BLOCKS_>>>(out);
}

// round 7
// speedup vs baseline: 1.1290x; 1.1290x over previous
#include <cuda_runtime.h>
#include <float.h>

// Shapes (fixed): network_mesh (4,3,32,32) f32 = d_in[0]; pc (4,3,4096) f32 = d_in[1].
// Output: scalar f32 = mean over 4*4096 nearest-refined-mesh squared distances.
#define B_       4
#define H_       32
#define W_       32
#define FAC_     3
#define OH_      94          // (32-1)*3+1
#define OW_      94
#define NMESH_   (OH_ * OW_) // 8836
#define M_       4096
#define SLICES_  55          // grid = 4*2*55 = 440 <= 444 = one full wave at 3 CTAs/SM
#define SLICE_   161         // ceil(8836/55); last slice = 142
#define THREADS_ 256
#define RPT_     4           // pc point PAIRS per thread (4 pairs = 8 points)
#define CHUNKS_  2           // 4096 pts / (256 thr * 8 pts)
#define R1BLOCKS_ 64

// Allocation-free scratch.
__device__ float g_partial[SLICES_ * B_ * M_];   // per-slice per-point minima (incl |p|^2)
__device__ float g_sums[R1BLOCKS_];

union df2 { unsigned long long u; float2 f; };

__device__ __forceinline__ unsigned long long pack2(float lo, float hi) {
    df2 t; t.f = make_float2(lo, hi); return t.u;
}

// Packed dual-FMA (Blackwell f32x2 path). No packed f32 min exists in PTX.
__device__ __forceinline__ unsigned long long fma2(unsigned long long a,
                                                   unsigned long long b,
                                                   unsigned long long c) {
    unsigned long long r;
    asm("fma.rn.f32x2 %0, %1, %2, %3;" : "=l"(r) : "l"(a), "l"(b), "l"(c));
    return r;
}

// ---------------------------------------------------------------------------
// Kernel 1: fused refine (inline, per-slice) + nearest-point partial minima.
// grid = (B, CHUNKS, SLICES) = (4,2,55) = 440 blocks: single wave, 3 CTAs/SM.
// smem holds the slice duplicated per lane-pair: sa[j]={xx,yy}, sb[j]={zz,ww}.
// __launch_bounds__(256,3) -> 85-reg budget; compiler used 79 in this config.
// ---------------------------------------------------------------------------
__global__ __launch_bounds__(THREADS_, 3)
void dist_kernel(const float* __restrict__ mesh, const float* __restrict__ pc) {
    __shared__ ulonglong2 sa[SLICE_];   // {x,x},{y,y}
    __shared__ ulonglong2 sb[SLICE_];   // {z,z},{w,w}  w = |m|^2

    const int b     = blockIdx.x;
    const int chunk = blockIdx.y;
    const int s     = blockIdx.z;

    const int base = s * SLICE_;
    const int cnt  = (base + SLICE_ <= NMESH_) ? SLICE_ : (NMESH_ - base);

    // --- Inline bilinear refine (align_corners, factor 3) for this slice ---
    const float* __restrict__ m0 = mesh + (b * 3 + 0) * H_ * W_;
    const float* __restrict__ m1 = mesh + (b * 3 + 1) * H_ * W_;
    const float* __restrict__ m2 = mesh + (b * 3 + 2) * H_ * W_;

    if (threadIdx.x < cnt) {
        int i = threadIdx.x;                 // SLICE_ <= THREADS_, one pass
        int idx = base + i;
        int r = idx / OW_;
        int c = idx - r * OW_;
        int y0 = r / FAC_; if (y0 > H_ - 2) y0 = H_ - 2;
        int x0 = c / FAC_; if (x0 > W_ - 2) x0 = W_ - 2;
        float wy = (float)r / (float)FAC_ - (float)y0;
        float wx = (float)c / (float)FAC_ - (float)x0;
        int o00 = y0 * W_ + x0, o01 = o00 + 1, o10 = o00 + W_, o11 = o10 + 1;

        float t0 = m0[o00] * (1.0f - wx) + m0[o01] * wx;
        float u0 = m0[o10] * (1.0f - wx) + m0[o11] * wx;
        float v0 = t0 * (1.0f - wy) + u0 * wy;

        float t1 = m1[o00] * (1.0f - wx) + m1[o01] * wx;
        float u1 = m1[o10] * (1.0f - wx) + m1[o11] * wx;
        float v1 = t1 * (1.0f - wy) + u1 * wy;

        float t2 = m2[o00] * (1.0f - wx) + m2[o01] * wx;
        float u2 = m2[o10] * (1.0f - wx) + m2[o11] * wx;
        float v2 = t2 * (1.0f - wy) + u2 * wy;

        float w = fmaf(v0, v0, fmaf(v1, v1, v2 * v2));

        sa[i] = make_ulonglong2(pack2(v0, v0), pack2(v1, v1));
        sb[i] = make_ulonglong2(pack2(v2, v2), pack2(w, w));
    }
    __syncthreads();

    // --- Load this thread's pc point pairs ---
    const float* __restrict__ px = pc + (b * 3 + 0) * M_;
    const float* __restrict__ py = pc + (b * 3 + 1) * M_;
    const float* __restrict__ pz = pc + (b * 3 + 2) * M_;

    const int q0 = chunk * (THREADS_ * RPT_) + threadIdx.x;   // pair index

    unsigned long long ax2[RPT_], ay2[RPT_], az2[RPT_];
    float pp0[RPT_], pp1[RPT_], b0[RPT_], b1[RPT_];
#pragma unroll
    for (int r = 0; r < RPT_; r++) {
        int q = q0 + r * THREADS_;
        float2 x = *(const float2*)(px + 2 * q);
        float2 y = *(const float2*)(py + 2 * q);
        float2 z = *(const float2*)(pz + 2 * q);
        ax2[r] = pack2(-2.0f * x.x, -2.0f * x.y);
        ay2[r] = pack2(-2.0f * y.x, -2.0f * y.y);
        az2[r] = pack2(-2.0f * z.x, -2.0f * z.y);
        pp0[r] = fmaf(x.x, x.x, fmaf(y.x, y.x, z.x * z.x));
        pp1[r] = fmaf(x.y, x.y, fmaf(y.y, y.y, z.y * z.y));
        b0[r] = FLT_MAX;
        b1[r] = FLT_MAX;
    }

    // --- Hot loop: t = fma2(xx,ax, fma2(yy,ay, fma2(zz,az, ww))); scalar min ---
#pragma unroll 2
    for (int j = 0; j < cnt; j++) {
        ulonglong2 A = sa[j];   // broadcast LDS.128
        ulonglong2 Bv = sb[j];
#pragma unroll
        for (int r = 0; r < RPT_; r++) {
            df2 t;
            t.u = fma2(A.x, ax2[r], fma2(A.y, ay2[r], fma2(Bv.x, az2[r], Bv.y)));
            b0[r] = fminf(b0[r], t.f.x);
            b1[r] = fminf(b1[r], t.f.y);
        }
    }

#pragma unroll
    for (int r = 0; r < RPT_; r++) {
        int q = q0 + r * THREADS_;
        float2 out = make_float2(b0[r] + pp0[r], b1[r] + pp1[r]);
        *(float2*)(g_partial + (s * B_ + b) * M_ + 2 * q) = out;
    }
}

// ---------------------------------------------------------------------------
// Kernel 2: per-point min across slices + per-block deterministic tree sum.
// ---------------------------------------------------------------------------
__global__ __launch_bounds__(THREADS_)
void reduce1_kernel() {
    __shared__ float red[THREADS_];
    const int i = blockIdx.x * THREADS_ + threadIdx.x;   // i < 16384
    float v = g_partial[i];
#pragma unroll
    for (int s = 1; s < SLICES_; s++)
        v = fminf(v, g_partial[s * (B_ * M_) + i]);
    red[threadIdx.x] = v;
    __syncthreads();
#pragma unroll
    for (int off = THREADS_ / 2; off > 0; off >>= 1) {
        if (threadIdx.x < off) red[threadIdx.x] += red[threadIdx.x + off];
        __syncthreads();
    }
    if (threadIdx.x == 0) g_sums[blockIdx.x] = red[0];
}

// ---------------------------------------------------------------------------
// Kernel 3: final deterministic sum of 64 partials + mean.
// ---------------------------------------------------------------------------
__global__ void reduce2_kernel(float* __restrict__ out) {
    __shared__ float red[R1BLOCKS_];
    red[threadIdx.x] = g_sums[threadIdx.x];
    __syncthreads();
#pragma unroll
    for (int off = R1BLOCKS_ / 2; off > 0; off >>= 1) {
        if (threadIdx.x < off) red[threadIdx.x] += red[threadIdx.x + off];
        __syncthreads();
    }
    if (threadIdx.x == 0) out[0] = red[0] / (float)(B_ * M_);
}

// ---------------------------------------------------------------------------
extern "C" void kernel_launch(void* const* d_in, const int* in_sizes, int n_in,
                              void* d_out, int out_size) {
    const float* mesh = (const float*)d_in[0];
    const float* pc   = (const float*)d_in[1];
    float* out = (float*)d_out;

    dim3 grid(B_, CHUNKS_, SLICES_);
    dist_kernel<<<grid, THREADS_>>>(mesh, pc);
    reduce1_kernel<<<R1BLOCKS_, THREADS_>>>();
    reduce2_kernel<<<1, R1BLOCKS_>>>(out);
}